// round 6
// baseline (speedup 1.0000x reference)
#include <cuda_runtime.h>
#include <cuda_bf16.h>
#include <math.h>

// Problem constants
#define TT 384   // sequence length (T2)
#define BB 128   // batch
#define HH 1024  // hidden
#define GG 3072  // 3*H gate width

// ---------------------------------------------------------------------------
// Scratch (device globals — no allocations allowed)
// ---------------------------------------------------------------------------
__device__ float g_xg[TT * BB * GG];    // precomputed input projections, [t][b][3H]
__device__ float g_seqA[TT * BB * HH];  // layer output ping, [t][b][H]
__device__ float g_seqB[TT * BB * HH];  // layer output pong
__device__ float g_h[2][BB * HH];       // hidden state double buffer

// Grid-barrier state (monotonic generation — safe across graph replays)
__device__ unsigned g_bar_count = 0;
__device__ volatile unsigned g_bar_gen = 0;

// ---------------------------------------------------------------------------
// Packed f32x2 helpers (Blackwell FFMA2 — PTX-only path)
// ---------------------------------------------------------------------------
__device__ __forceinline__ unsigned long long pk2(float lo, float hi) {
    unsigned long long r;
    asm("mov.b64 %0, {%1, %2};" : "=l"(r) : "f"(lo), "f"(hi));
    return r;
}
__device__ __forceinline__ void fma2(unsigned long long& d, unsigned long long a,
                                     unsigned long long b) {
    asm("fma.rn.f32x2 %0, %1, %2, %0;" : "+l"(d) : "l"(a), "l"(b));
}
__device__ __forceinline__ float2 upk2(unsigned long long v) {
    float lo, hi;
    asm("mov.b64 {%0, %1}, %2;" : "=f"(lo), "=f"(hi) : "l"(v));
    return make_float2(lo, hi);
}
__device__ __forceinline__ float sigm(float x) { return 1.0f / (1.0f + __expf(-x)); }
__device__ __forceinline__ float tanh_f(float x) {
    return 2.0f / (1.0f + __expf(-2.0f * x)) - 1.0f;
}

// Sense-reversing grid barrier. All gridDim.x blocks MUST be co-resident.
__device__ __forceinline__ void grid_barrier(unsigned& gen) {
    __syncthreads();
    if (threadIdx.x == 0) {
        __threadfence();  // release: publish this block's writes
        if (atomicAdd(&g_bar_count, 1u) == gridDim.x - 1) {
            g_bar_count = 0;
            __threadfence();          // reset visible before generation bump
            g_bar_gen = gen + 1;
        } else {
            while (g_bar_gen == gen) { }
        }
        __threadfence();  // acquire
        gen++;
    }
    __syncthreads();
}

// ---------------------------------------------------------------------------
// Transpose rand_input (B,T,H) -> g_seqA (T,B,H)
// ---------------------------------------------------------------------------
__global__ __launch_bounds__(256) void transpose_k(const float* __restrict__ in) {
    int o = blockIdx.x * 256 + threadIdx.x;
    int h = o % HH;
    int tb = o / HH;
    int b = tb % BB;
    int t = tb / BB;
    g_seqA[o] = in[(b * TT + t) * HH + h];
}

// ---------------------------------------------------------------------------
// Projection GEMM: g_xg[M=T*B][3072] = A[M][1024] @ W[3072][1024]^T + bias
// Block tile 128x64, BK=16, 256 threads, per-thread 8x4 via f32x2 (pairs on M)
// sB rows padded to 68 floats (272B, 16B-aligned) so the 4 w operands load as
// one LDS.128; per-k issue mix 25 vs 32 fma-cycles -> fma-pipe-bound.
// ---------------------------------------------------------------------------
__global__ __launch_bounds__(256) void proj_k(int srcSel, const float* __restrict__ W,
                                              const float* __restrict__ bias) {
    const float* A = srcSel ? g_seqB : g_seqA;
    __shared__ float sA[16][130];  // [k][m], 520B rows keep LDS.64 aligned
    __shared__ float sB[16][68];   // [k][n], 272B rows keep LDS.128 aligned
    int tid = threadIdx.x;
    int tx = tid & 15, ty = tid >> 4;
    int m0 = blockIdx.x * 128;
    int n0 = blockIdx.y * 64;

    unsigned long long acc[4][4];
#pragma unroll
    for (int p = 0; p < 4; p++)
#pragma unroll
        for (int q = 0; q < 4; q++) acc[p][q] = 0ull;

    for (int k0 = 0; k0 < HH; k0 += 16) {
#pragma unroll
        for (int l = 0; l < 2; l++) {
            int f = tid + l * 256;  // 512 float4 = 128x16
            int r = f >> 2, c4 = f & 3;
            float4 v = *(const float4*)&A[(m0 + r) * HH + k0 + c4 * 4];
            sA[c4 * 4 + 0][r] = v.x;
            sA[c4 * 4 + 1][r] = v.y;
            sA[c4 * 4 + 2][r] = v.z;
            sA[c4 * 4 + 3][r] = v.w;
        }
        {
            int n = tid >> 2, c4 = tid & 3;  // 256 float4 = 64x16
            float4 v = *(const float4*)&W[(n0 + n) * HH + k0 + c4 * 4];
            sB[c4 * 4 + 0][n] = v.x;
            sB[c4 * 4 + 1][n] = v.y;
            sB[c4 * 4 + 2][n] = v.z;
            sB[c4 * 4 + 3][n] = v.w;
        }
        __syncthreads();
#pragma unroll
        for (int k = 0; k < 16; k++) {
            unsigned long long a01 = *(const unsigned long long*)&sA[k][ty * 8 + 0];
            unsigned long long a23 = *(const unsigned long long*)&sA[k][ty * 8 + 2];
            unsigned long long a45 = *(const unsigned long long*)&sA[k][ty * 8 + 4];
            unsigned long long a67 = *(const unsigned long long*)&sA[k][ty * 8 + 6];
            float4 wv = *(const float4*)&sB[k][tx * 4];  // LDS.128
            float wq[4] = {wv.x, wv.y, wv.z, wv.w};
#pragma unroll
            for (int q = 0; q < 4; q++) {
                unsigned long long wp = pk2(wq[q], wq[q]);
                fma2(acc[0][q], a01, wp);
                fma2(acc[1][q], a23, wp);
                fma2(acc[2][q], a45, wp);
                fma2(acc[3][q], a67, wp);
            }
        }
        __syncthreads();
    }
    // Epilogue: bias once (LDG.128), two STG.128 per accumulator row-pair.
    int nb = n0 + tx * 4;  // 16B-aligned column base
    float4 bv = *(const float4*)&bias[nb];
#pragma unroll
    for (int p = 0; p < 4; p++) {
        int m = m0 + ty * 8 + 2 * p;
        float2 v0 = upk2(acc[p][0]);
        float2 v1 = upk2(acc[p][1]);
        float2 v2 = upk2(acc[p][2]);
        float2 v3 = upk2(acc[p][3]);
        float4 lo = make_float4(v0.x + bv.x, v1.x + bv.y, v2.x + bv.z, v3.x + bv.w);
        float4 hi = make_float4(v0.y + bv.x, v1.y + bv.y, v2.y + bv.z, v3.y + bv.w);
        *(float4*)&g_xg[m * GG + nb] = lo;
        *(float4*)&g_xg[(m + 1) * GG + nb] = hi;
    }
}

// ---------------------------------------------------------------------------
// Persistent recurrent kernel: runs all TT GRU steps for one layer.
// 128 blocks x 128 threads (co-resident: 17KB smem, 1 block/SM). Block owns
// 8 hidden cols j (24 gate rows) x 128 batch x K=1024 (BK=32). Thread: 1 j x
// 8 batches -> 12 f32x2 accumulators (fma-pipe-bound inner loop).
// h staged via __ldcs (streaming) so the per-block Whh slice stays L1-hot
// across steps (persistent kernel => no per-launch L1D flush).
// ---------------------------------------------------------------------------
__global__ __launch_bounds__(128) void step_persist(const float* __restrict__ Whh,
                                                    const float* __restrict__ bhh,
                                                    int outSel,
                                                    const float* __restrict__ h0src) {
    __shared__ float sh[32][130];    // [k][b], 520B rows (8B-aligned for LDS.64)
    __shared__ float sw[3][8][33];   // [gate][jj][k]
    int tid = threadIdx.x;
    int bx = tid & 7;    // j within tile
    int by = tid >> 3;   // 0..15 -> batch rows 8by..8by+7
    int j0 = blockIdx.x * 8;
    int j = j0 + bx;

    unsigned gen = g_bar_gen;  // entry snapshot (read before this block arrives)

    // Init h (this block's 8 columns across all batches), then sync grid.
#pragma unroll
    for (int i = 0; i < 8; i++) {
        int b = 8 * by + i;
        g_h[0][b * HH + j] = h0src ? h0src[b * HH + j] : 0.0f;
    }
    grid_barrier(gen);

    float br = bhh[j], bz = bhh[HH + j], bn = bhh[2 * HH + j];
    float* outseq = (outSel == 0) ? g_seqA : g_seqB;

    for (int t = 0; t < TT; t++) {
        const float* h_in = g_h[t & 1];
        float* h_out = g_h[(t + 1) & 1];

        unsigned long long acc[3][4];
#pragma unroll
        for (int g = 0; g < 3; g++)
#pragma unroll
            for (int p = 0; p < 4; p++) acc[g][p] = 0ull;

        for (int k0 = 0; k0 < HH; k0 += 32) {
#pragma unroll
            for (int l = 0; l < 8; l++) {
                int f = tid + l * 128;          // 1024 float4 = 128 rows x 32 k
                int r = f >> 3, c4 = f & 7;
                float4 v = __ldcs((const float4*)&h_in[r * HH + k0 + c4 * 4]);
                sh[c4 * 4 + 0][r] = v.x;
                sh[c4 * 4 + 1][r] = v.y;
                sh[c4 * 4 + 2][r] = v.z;
                sh[c4 * 4 + 3][r] = v.w;
            }
#pragma unroll
            for (int f = tid; f < 192; f += 128) {  // 24 rows x 32 k = 192 float4
                int col = f >> 3, c4 = f & 7;
                int gate = col >> 3, jj = col & 7;
                float4 v = *(const float4*)&Whh[(gate * HH + j0 + jj) * HH + k0 + c4 * 4];
                sw[gate][jj][c4 * 4 + 0] = v.x;
                sw[gate][jj][c4 * 4 + 1] = v.y;
                sw[gate][jj][c4 * 4 + 2] = v.z;
                sw[gate][jj][c4 * 4 + 3] = v.w;
            }
            __syncthreads();
#pragma unroll
            for (int k = 0; k < 32; k++) {
                unsigned long long h01 = *(const unsigned long long*)&sh[k][8 * by + 0];
                unsigned long long h23 = *(const unsigned long long*)&sh[k][8 * by + 2];
                unsigned long long h45 = *(const unsigned long long*)&sh[k][8 * by + 4];
                unsigned long long h67 = *(const unsigned long long*)&sh[k][8 * by + 6];
                float wr = sw[0][bx][k], wz = sw[1][bx][k], wn = sw[2][bx][k];
                unsigned long long wrp = pk2(wr, wr);
                unsigned long long wzp = pk2(wz, wz);
                unsigned long long wnp = pk2(wn, wn);
                fma2(acc[0][0], h01, wrp);
                fma2(acc[0][1], h23, wrp);
                fma2(acc[0][2], h45, wrp);
                fma2(acc[0][3], h67, wrp);
                fma2(acc[1][0], h01, wzp);
                fma2(acc[1][1], h23, wzp);
                fma2(acc[1][2], h45, wzp);
                fma2(acc[1][3], h67, wzp);
                fma2(acc[2][0], h01, wnp);
                fma2(acc[2][1], h23, wnp);
                fma2(acc[2][2], h45, wnp);
                fma2(acc[2][3], h67, wnp);
            }
            __syncthreads();
        }

        float hrv[8], hzv[8], hnv[8];
#pragma unroll
        for (int p = 0; p < 4; p++) {
            float2 vr = upk2(acc[0][p]);
            float2 vz = upk2(acc[1][p]);
            float2 vn = upk2(acc[2][p]);
            hrv[2 * p] = vr.x; hrv[2 * p + 1] = vr.y;
            hzv[2 * p] = vz.x; hzv[2 * p + 1] = vz.y;
            hnv[2 * p] = vn.x; hnv[2 * p + 1] = vn.y;
        }
#pragma unroll
        for (int i = 0; i < 8; i++) {
            int b = 8 * by + i;
            const float* xg = &g_xg[(t * BB + b) * GG];
            float xr = xg[j], xz = xg[HH + j], xn = xg[2 * HH + j];
            float r = sigm(xr + hrv[i] + br);
            float z = sigm(xz + hzv[i] + bz);
            float n = tanh_f(xn + r * (hnv[i] + bn));
            float hold = h_in[b * HH + j];
            float hnew = (1.0f - z) * n + z * hold;
            h_out[b * HH + j] = hnew;
            if (outSel < 2) outseq[(t * BB + b) * HH + j] = hnew;
        }

        grid_barrier(gen);  // step t writes visible before step t+1 reuses buffers
    }
}

// ---------------------------------------------------------------------------
// predictions[b] = dot(h_last[b], lin_W) + lin_b   (h_last in g_h[0]: TT even)
// ---------------------------------------------------------------------------
__global__ __launch_bounds__(256) void final_k(const float* __restrict__ W,
                                               const float* __restrict__ bv,
                                               float* __restrict__ out) {
    __shared__ float red[256];
    int b = blockIdx.x;
    float s = 0.0f;
    for (int k = threadIdx.x; k < HH; k += 256) s += g_h[0][b * HH + k] * W[k];
    red[threadIdx.x] = s;
    __syncthreads();
    for (int st = 128; st > 0; st >>= 1) {
        if (threadIdx.x < st) red[threadIdx.x] += red[threadIdx.x + st];
        __syncthreads();
    }
    if (threadIdx.x == 0) out[b] = red[0] + bv[0];
}

// ---------------------------------------------------------------------------
// Launch: the GRUCell branch is multiplied by exactly 0.0 downstream (finite
// sum), so it is skipped entirely. split/concat is identity. 4 GRU layer-runs:
//   run1: L0(h0[0]) -> L1(h0[1]) ; run2: L0(0) -> L1(0) -> h_last -> linear.
// ---------------------------------------------------------------------------
extern "C" void kernel_launch(void* const* d_in, const int* in_sizes, int n_in,
                              void* d_out, int out_size) {
    const float* rand_input = (const float*)d_in[1];
    const float* h0   = (const float*)d_in[2];
    const float* Wih0 = (const float*)d_in[7];
    const float* Whh0 = (const float*)d_in[8];
    const float* bih0 = (const float*)d_in[9];
    const float* bhh0 = (const float*)d_in[10];
    const float* Wih1 = (const float*)d_in[11];
    const float* Whh1 = (const float*)d_in[12];
    const float* bih1 = (const float*)d_in[13];
    const float* bhh1 = (const float*)d_in[14];
    const float* linW = (const float*)d_in[15];
    const float* linb = (const float*)d_in[16];
    float* out = (float*)d_out;

    dim3 pg(TT * BB / 128, GG / 64);  // 384 x 48

    transpose_k<<<TT * BB * HH / 256, 256>>>(rand_input);  // -> g_seqA

    // run 1, layer 0: seqA -> seqB, h = h0[0]
    proj_k<<<pg, 256>>>(0, Wih0, bih0);
    step_persist<<<HH / 8, 128>>>(Whh0, bhh0, 1, h0);

    // run 1, layer 1: seqB -> seqA, h = h0[1]
    proj_k<<<pg, 256>>>(1, Wih1, bih1);
    step_persist<<<HH / 8, 128>>>(Whh1, bhh1, 0, h0 + BB * HH);

    // run 2, layer 0: seqA -> seqB, h = 0
    proj_k<<<pg, 256>>>(0, Wih0, bih0);
    step_persist<<<HH / 8, 128>>>(Whh0, bhh0, 1, nullptr);

    // run 2, layer 1: seqB -> (h only), h = 0
    proj_k<<<pg, 256>>>(1, Wih1, bih1);
    step_persist<<<HH / 8, 128>>>(Whh1, bhh1, 2, nullptr);

    final_k<<<BB, 256>>>(linW, linb, out);
}

// round 8
// speedup vs baseline: 1.3126x; 1.3126x over previous
#include <cuda_runtime.h>
#include <cuda_bf16.h>
#include <math.h>

// Problem constants
#define TT 384   // sequence length (T2)
#define BB 128   // batch
#define HH 1024  // hidden
#define GG 3072  // 3*H gate width

// step_persist smem layout (dynamic): Whh slice + double-buffered h tile
#define SW_ROW 1036                    // padded row stride (mod32=12: conflict-free; 4144B rows, 16B-aligned)
#define SW_FLOATS (24 * SW_ROW)        // 24 gate rows x 1024 (padded)
#define SH_PAD 132                     // 528B rows: 16B-aligned, conflict-free LDS.64
#define SH_FLOATS (2 * 32 * SH_PAD)    // [buf][k][b]
#define STEP_SMEM ((SW_FLOATS + SH_FLOATS) * 4)   // ~133 KB (< 228 KB: 1 block/SM, all 128 co-resident)

// ---------------------------------------------------------------------------
// Scratch (device globals — no allocations allowed)
// ---------------------------------------------------------------------------
__device__ float g_xg[TT * BB * GG];    // input projections, [t][b][3H]
__device__ float g_seqA[TT * BB * HH];  // layer output ping, [t][b][H]
__device__ float g_seqB[TT * BB * HH];  // layer output pong
__device__ float g_h[2][BB * HH];       // hidden state double buffer

// Grid-barrier state (monotonic generation — safe across graph replays)
__device__ unsigned g_bar_count = 0;
__device__ volatile unsigned g_bar_gen = 0;

// ---------------------------------------------------------------------------
// Packed f32x2 helpers (Blackwell FFMA2 — PTX-only path)
// ---------------------------------------------------------------------------
__device__ __forceinline__ unsigned long long pk2(float lo, float hi) {
    unsigned long long r;
    asm("mov.b64 %0, {%1, %2};" : "=l"(r) : "f"(lo), "f"(hi));
    return r;
}
__device__ __forceinline__ void fma2(unsigned long long& d, unsigned long long a,
                                     unsigned long long b) {
    asm("fma.rn.f32x2 %0, %1, %2, %0;" : "+l"(d) : "l"(a), "l"(b));
}
__device__ __forceinline__ float2 upk2(unsigned long long v) {
    float lo, hi;
    asm("mov.b64 {%0, %1}, %2;" : "=f"(lo), "=f"(hi) : "l"(v));
    return make_float2(lo, hi);
}
__device__ __forceinline__ float sigm(float x) { return 1.0f / (1.0f + __expf(-x)); }
__device__ __forceinline__ float tanh_f(float x) {
    return 2.0f / (1.0f + __expf(-2.0f * x)) - 1.0f;
}

// Sense-reversing grid barrier. All gridDim.x blocks MUST be co-resident.
// NOTE: tid0's __threadfence() emits CCTL.IVALL (flushes L1D) — this is why
// step-invariant data (Whh) lives in SMEM, not L1.
__device__ __forceinline__ void grid_barrier(unsigned& gen) {
    __syncthreads();
    if (threadIdx.x == 0) {
        __threadfence();  // release: publish this block's writes
        if (atomicAdd(&g_bar_count, 1u) == gridDim.x - 1) {
            g_bar_count = 0;
            __threadfence();          // reset visible before generation bump
            g_bar_gen = gen + 1;
        } else {
            while (g_bar_gen == gen) { }
        }
        __threadfence();  // acquire
        gen++;
    }
    __syncthreads();
}

// ---------------------------------------------------------------------------
// Transpose rand_input (B,T,H) -> g_seqA (T,B,H)
// ---------------------------------------------------------------------------
__global__ __launch_bounds__(256) void transpose_k(const float* __restrict__ in) {
    int o = blockIdx.x * 256 + threadIdx.x;
    int h = o % HH;
    int tb = o / HH;
    int b = tb % BB;
    int t = tb / BB;
    g_seqA[o] = in[(b * TT + t) * HH + h];
}

// ---------------------------------------------------------------------------
// Projection GEMM: g_xg[M=T*B][3072] = A[M][1024] @ W[3072][1024]^T + bias
// Block tile 128x64, BK=16, 256 threads, per-thread 8x4 via f32x2.
// minBlocks=4 to lift reg-limited occupancy (measured occ 37.2%, fma 63.9%).
// ---------------------------------------------------------------------------
__global__ __launch_bounds__(256, 4) void proj_k(int srcSel, const float* __restrict__ W,
                                                 const float* __restrict__ bias) {
    const float* A = srcSel ? g_seqB : g_seqA;
    __shared__ float sA[16][130];  // [k][m], 520B rows keep LDS.64 aligned
    __shared__ float sB[16][68];   // [k][n], 272B rows keep LDS.128 aligned
    int tid = threadIdx.x;
    int tx = tid & 15, ty = tid >> 4;
    int m0 = blockIdx.x * 128;
    int n0 = blockIdx.y * 64;

    unsigned long long acc[4][4];
#pragma unroll
    for (int p = 0; p < 4; p++)
#pragma unroll
        for (int q = 0; q < 4; q++) acc[p][q] = 0ull;

    for (int k0 = 0; k0 < HH; k0 += 16) {
#pragma unroll
        for (int l = 0; l < 2; l++) {
            int f = tid + l * 256;  // 512 float4 = 128x16
            int r = f >> 2, c4 = f & 3;
            float4 v = *(const float4*)&A[(m0 + r) * HH + k0 + c4 * 4];
            sA[c4 * 4 + 0][r] = v.x;
            sA[c4 * 4 + 1][r] = v.y;
            sA[c4 * 4 + 2][r] = v.z;
            sA[c4 * 4 + 3][r] = v.w;
        }
        {
            int n = tid >> 2, c4 = tid & 3;  // 256 float4 = 64x16
            float4 v = *(const float4*)&W[(n0 + n) * HH + k0 + c4 * 4];
            sB[c4 * 4 + 0][n] = v.x;
            sB[c4 * 4 + 1][n] = v.y;
            sB[c4 * 4 + 2][n] = v.z;
            sB[c4 * 4 + 3][n] = v.w;
        }
        __syncthreads();
#pragma unroll
        for (int k = 0; k < 16; k++) {
            unsigned long long a01 = *(const unsigned long long*)&sA[k][ty * 8 + 0];
            unsigned long long a23 = *(const unsigned long long*)&sA[k][ty * 8 + 2];
            unsigned long long a45 = *(const unsigned long long*)&sA[k][ty * 8 + 4];
            unsigned long long a67 = *(const unsigned long long*)&sA[k][ty * 8 + 6];
            float4 wv = *(const float4*)&sB[k][tx * 4];  // LDS.128
            float wq[4] = {wv.x, wv.y, wv.z, wv.w};
#pragma unroll
            for (int q = 0; q < 4; q++) {
                unsigned long long wp = pk2(wq[q], wq[q]);
                fma2(acc[0][q], a01, wp);
                fma2(acc[1][q], a23, wp);
                fma2(acc[2][q], a45, wp);
                fma2(acc[3][q], a67, wp);
            }
        }
        __syncthreads();
    }
    int nb = n0 + tx * 4;  // 16B-aligned column base
    float4 bv = *(const float4*)&bias[nb];
#pragma unroll
    for (int p = 0; p < 4; p++) {
        int m = m0 + ty * 8 + 2 * p;
        float2 v0 = upk2(acc[p][0]);
        float2 v1 = upk2(acc[p][1]);
        float2 v2 = upk2(acc[p][2]);
        float2 v3 = upk2(acc[p][3]);
        float4 lo = make_float4(v0.x + bv.x, v1.x + bv.y, v2.x + bv.z, v3.x + bv.w);
        float4 hi = make_float4(v0.y + bv.x, v1.y + bv.y, v2.y + bv.z, v3.y + bv.w);
        *(float4*)&g_xg[m * GG + nb] = lo;
        *(float4*)&g_xg[(m + 1) * GG + nb] = hi;
    }
}

// ---------------------------------------------------------------------------
// Persistent recurrent kernel v2: Whh slice resident in SMEM (loaded once —
// immune to the per-barrier L1D flush); h streamed via register-staged,
// double-buffered smem tiles (prefetch overlaps compute; 1 sync/stage).
// Weights read as LDS.128 per gate per 4 k (bank-disjoint across bx lanes).
// 128 blocks x 256 threads. Thread: 1 j x 4 batches -> 6 f32x2 accumulators.
// ---------------------------------------------------------------------------
__global__ __launch_bounds__(256) void step_persist(const float* __restrict__ Whh,
                                                    const float* __restrict__ bhh,
                                                    int outSel,
                                                    const float* __restrict__ h0src) {
    extern __shared__ float dsm[];
    float* sw = dsm;                 // [24][SW_ROW] gate rows (r*, z*, n*)
    float* sh = dsm + SW_FLOATS;     // [2][32][SH_PAD] = [buf][k][b]
    int tid = threadIdx.x;
    int bx = tid & 7;    // j within tile
    int by = tid >> 3;   // 0..31 -> batch rows 4by..4by+3
    int j0 = blockIdx.x * 8;
    int j = j0 + bx;

    unsigned gen = g_bar_gen;  // entry snapshot (read before this block arrives)

    // Load this block's Whh slice (24 rows x 1024) into smem ONCE.
    for (int f = tid; f < 24 * 256; f += 256) {  // 6144 float4
        int r = f >> 8, c = f & 255;             // r 0..23, c = float4 index
        int gate = r >> 3, jj = r & 7;
        float4 v = *(const float4*)&Whh[(gate * HH + j0 + jj) * HH + c * 4];
        *(float4*)&sw[r * SW_ROW + c * 4] = v;
    }
    // Init h (this block's 8 columns across all batches).
#pragma unroll
    for (int i = 0; i < 4; i++) {
        int b = 4 * by + i;
        g_h[0][b * HH + j] = h0src ? h0src[b * HH + j] : 0.0f;
    }
    grid_barrier(gen);  // also orders the smem sw fill (starts with syncthreads)

    float br = bhh[j], bz = bhh[HH + j], bn = bhh[2 * HH + j];
    const float* swr = &sw[(0 * 8 + bx) * SW_ROW];
    const float* swz = &sw[(1 * 8 + bx) * SW_ROW];
    const float* swn = &sw[(2 * 8 + bx) * SW_ROW];
    float* outseq = (outSel == 0) ? g_seqA : g_seqB;

    int ldr = tid >> 3, ldc4 = tid & 7;  // staging map: 4 f4/thread per 32k stage

    for (int t = 0; t < TT; t++) {
        const float* h_in = g_h[t & 1];
        float* h_out = g_h[(t + 1) & 1];

        // Prologue: fetch stage 0, store to buf 0.
        float4 st[4];
#pragma unroll
        for (int l = 0; l < 4; l++) {
            int f = tid + l * 256;
            int r = f >> 3, c4 = f & 7;
            st[l] = __ldcs((const float4*)&h_in[r * HH + c4 * 4]);
        }
#pragma unroll
        for (int l = 0; l < 4; l++) {
            int f = tid + l * 256;
            int r = f >> 3, c4 = f & 7;
            float* d = &sh[0 * (32 * SH_PAD) + (c4 * 4) * SH_PAD + r];
            d[0 * SH_PAD] = st[l].x;
            d[1 * SH_PAD] = st[l].y;
            d[2 * SH_PAD] = st[l].z;
            d[3 * SH_PAD] = st[l].w;
        }
        __syncthreads();

        unsigned long long accR0 = 0, accR1 = 0, accZ0 = 0, accZ1 = 0, accN0 = 0, accN1 = 0;

        for (int s = 0; s < 32; s++) {
            int buf = s & 1;
            if (s + 1 < 32) {  // prefetch next stage into registers (overlaps compute)
                int k0n = (s + 1) * 32;
#pragma unroll
                for (int l = 0; l < 4; l++) {
                    int f = tid + l * 256;
                    int r = f >> 3, c4 = f & 7;
                    st[l] = __ldcs((const float4*)&h_in[r * HH + k0n + c4 * 4]);
                }
            }
            const float* shb = &sh[buf * (32 * SH_PAD)];
            int kg0 = s * 32;
#pragma unroll
            for (int k4 = 0; k4 < 32; k4 += 4) {
                float4 wrv = *(const float4*)&swr[kg0 + k4];  // LDS.128, bank-disjoint per bx
                float4 wzv = *(const float4*)&swz[kg0 + k4];
                float4 wnv = *(const float4*)&swn[kg0 + k4];
                float wr4[4] = {wrv.x, wrv.y, wrv.z, wrv.w};
                float wz4[4] = {wzv.x, wzv.y, wzv.z, wzv.w};
                float wn4[4] = {wnv.x, wnv.y, wnv.z, wnv.w};
#pragma unroll
                for (int kk = 0; kk < 4; kk++) {
                    int k = k4 + kk;
                    unsigned long long h01 =
                        *(const unsigned long long*)&shb[k * SH_PAD + 4 * by + 0];
                    unsigned long long h23 =
                        *(const unsigned long long*)&shb[k * SH_PAD + 4 * by + 2];
                    unsigned long long wrp = pk2(wr4[kk], wr4[kk]);
                    unsigned long long wzp = pk2(wz4[kk], wz4[kk]);
                    unsigned long long wnp = pk2(wn4[kk], wn4[kk]);
                    fma2(accR0, h01, wrp);
                    fma2(accR1, h23, wrp);
                    fma2(accZ0, h01, wzp);
                    fma2(accZ1, h23, wzp);
                    fma2(accN0, h01, wnp);
                    fma2(accN1, h23, wnp);
                }
            }
            if (s + 1 < 32) {  // stage s compute done -> store next into buf^1
                float* d = &sh[(buf ^ 1) * (32 * SH_PAD) + (ldc4 * 4) * SH_PAD + ldr];
#pragma unroll
                for (int l = 0; l < 4; l++) {
                    float* dl = d + l * 32;  // +256 threads => +32 batch rows
                    dl[0 * SH_PAD] = st[l].x;
                    dl[1 * SH_PAD] = st[l].y;
                    dl[2 * SH_PAD] = st[l].z;
                    dl[3 * SH_PAD] = st[l].w;
                }
                __syncthreads();  // separates "store buf^1" from "compute buf^1"
            }
        }

        float2 r01 = upk2(accR0), r23 = upk2(accR1);
        float2 z01 = upk2(accZ0), z23 = upk2(accZ1);
        float2 n01 = upk2(accN0), n23 = upk2(accN1);
        float hrv[4] = {r01.x, r01.y, r23.x, r23.y};
        float hzv[4] = {z01.x, z01.y, z23.x, z23.y};
        float hnv[4] = {n01.x, n01.y, n23.x, n23.y};
#pragma unroll
        for (int i = 0; i < 4; i++) {
            int b = 4 * by + i;
            const float* xg = &g_xg[(t * BB + b) * GG];
            float xr = xg[j], xz = xg[HH + j], xn = xg[2 * HH + j];
            float r = sigm(xr + hrv[i] + br);
            float z = sigm(xz + hzv[i] + bz);
            float n = tanh_f(xn + r * (hnv[i] + bn));
            float hold = h_in[b * HH + j];
            float hnew = (1.0f - z) * n + z * hold;
            h_out[b * HH + j] = hnew;
            if (outSel < 2) outseq[(t * BB + b) * HH + j] = hnew;
        }

        grid_barrier(gen);  // step t writes visible before step t+1 reuses buffers
    }
}

// ---------------------------------------------------------------------------
// predictions[b] = dot(h_last[b], lin_W) + lin_b   (h_last in g_h[0]: TT even)
// ---------------------------------------------------------------------------
__global__ __launch_bounds__(256) void final_k(const float* __restrict__ W,
                                               const float* __restrict__ bv,
                                               float* __restrict__ out) {
    __shared__ float red[256];
    int b = blockIdx.x;
    float s = 0.0f;
    for (int k = threadIdx.x; k < HH; k += 256) s += g_h[0][b * HH + k] * W[k];
    red[threadIdx.x] = s;
    __syncthreads();
    for (int st = 128; st > 0; st >>= 1) {
        if (threadIdx.x < st) red[threadIdx.x] += red[threadIdx.x + st];
        __syncthreads();
    }
    if (threadIdx.x == 0) out[b] = red[0] + bv[0];
}

// ---------------------------------------------------------------------------
// Launch: the GRUCell branch is multiplied by exactly 0.0 downstream (finite
// sum), so it is skipped entirely. split/concat is identity. 4 GRU layer-runs:
//   run1: L0(h0[0]) -> L1(h0[1]) ; run2: L0(0) -> L1(0) -> h_last -> linear.
// ---------------------------------------------------------------------------
extern "C" void kernel_launch(void* const* d_in, const int* in_sizes, int n_in,
                              void* d_out, int out_size) {
    const float* rand_input = (const float*)d_in[1];
    const float* h0   = (const float*)d_in[2];
    const float* Wih0 = (const float*)d_in[7];
    const float* Whh0 = (const float*)d_in[8];
    const float* bih0 = (const float*)d_in[9];
    const float* bhh0 = (const float*)d_in[10];
    const float* Wih1 = (const float*)d_in[11];
    const float* Whh1 = (const float*)d_in[12];
    const float* bih1 = (const float*)d_in[13];
    const float* bhh1 = (const float*)d_in[14];
    const float* linW = (const float*)d_in[15];
    const float* linb = (const float*)d_in[16];
    float* out = (float*)d_out;

    cudaFuncSetAttribute(step_persist, cudaFuncAttributeMaxDynamicSharedMemorySize,
                         STEP_SMEM);

    dim3 pg(TT * BB / 128, GG / 64);  // 384 x 48

    transpose_k<<<TT * BB * HH / 256, 256>>>(rand_input);  // -> g_seqA

    // run 1, layer 0: seqA -> seqB, h = h0[0]
    proj_k<<<pg, 256>>>(0, Wih0, bih0);
    step_persist<<<HH / 8, 256, STEP_SMEM>>>(Whh0, bhh0, 1, h0);

    // run 1, layer 1: seqB -> seqA, h = h0[1]
    proj_k<<<pg, 256>>>(1, Wih1, bih1);
    step_persist<<<HH / 8, 256, STEP_SMEM>>>(Whh1, bhh1, 0, h0 + BB * HH);

    // run 2, layer 0: seqA -> seqB, h = 0
    proj_k<<<pg, 256>>>(0, Wih0, bih0);
    step_persist<<<HH / 8, 256, STEP_SMEM>>>(Whh0, bhh0, 1, nullptr);

    // run 2, layer 1: seqB -> (h only), h = 0
    proj_k<<<pg, 256>>>(1, Wih1, bih1);
    step_persist<<<HH / 8, 256, STEP_SMEM>>>(Whh1, bhh1, 2, nullptr);

    final_k<<<BB, 256>>>(linW, linb, out);
}